// round 4
// baseline (speedup 1.0000x reference)
#include <cuda_runtime.h>
#include <cuda_bf16.h>
#include <cstdint>

// ---------------- problem constants ----------------
constexpr int Bb   = 4;
constexpr int Tt   = 128;
constexpr int Vv   = 50257;
constexpr int LSRC = 512;
constexpr int Dd   = 512;
constexpr int Mm   = Bb * Tt;          // 512 rows
constexpr int KPAD = 50304;            // multiple of 64 (>= Vv)
constexpr int BK   = 32;
constexpr int NKT  = KPAD / BK;        // 1572 k-tiles of 32
constexpr int KSPLIT = 9;
constexpr int SPLIT_ITERS = (NKT + KSPLIT - 1) / KSPLIT;   // 175

// ---------------- device scratch (no allocs allowed) ----------------
__device__ __nv_bfloat16 g_A [(size_t)Mm * KPAD];          // exp(output_mle), bf16, K-padded
__device__ __nv_bfloat16 g_Wt[(size_t)Dd * KPAD];          // W_emb transposed [D, K], bf16
__device__ float g_part[(size_t)KSPLIT * Mm * Dd];         // per-ksplit GEMM partials
__device__ float g_cov, g_nll, g_cnt, g_cos, g_dec;

// ---------------- helpers ----------------
__device__ __forceinline__ uint32_t smem_u32(const void* p) {
    return (uint32_t)__cvta_generic_to_shared(p);
}
__device__ __forceinline__ uint32_t sw64(uint32_t x) {      // SW64 swizzle for 64B rows
    return x ^ ((x >> 3) & 0x30);
}
__device__ __forceinline__ void cp_async16(uint32_t saddr, const void* gaddr) {
    asm volatile("cp.async.cg.shared.global [%0], [%1], 16;" :: "r"(saddr), "l"(gaddr));
}
__device__ __forceinline__ void cp_commit() {
    asm volatile("cp.async.commit_group;" ::: "memory");
}
__device__ __forceinline__ void cp_wait1() {
    asm volatile("cp.async.wait_group 1;" ::: "memory");
}
__device__ __forceinline__ void ldm4(uint32_t& r0, uint32_t& r1, uint32_t& r2, uint32_t& r3,
                                     uint32_t addr) {
    asm volatile("ldmatrix.sync.aligned.m8n8.x4.shared.b16 {%0,%1,%2,%3}, [%4];"
                 : "=r"(r0), "=r"(r1), "=r"(r2), "=r"(r3) : "r"(addr));
}
__device__ __forceinline__ void mma16816(float* c, uint32_t a0, uint32_t a1, uint32_t a2,
                                         uint32_t a3, uint32_t b0, uint32_t b1) {
    asm volatile("mma.sync.aligned.m16n8k16.row.col.f32.bf16.bf16.f32 "
                 "{%0,%1,%2,%3}, {%4,%5,%6,%7}, {%8,%9}, {%0,%1,%2,%3};"
                 : "+f"(c[0]), "+f"(c[1]), "+f"(c[2]), "+f"(c[3])
                 : "r"(a0), "r"(a1), "r"(a2), "r"(a3), "r"(b0), "r"(b1));
}

// ---------------- kernels ----------------
__global__ void k_zero() { g_cov = 0.f; g_nll = 0.f; g_cnt = 0.f; g_cos = 0.f; }

// A = bf16(exp(output_mle)) with zero K-padding.  grid: (ceil(KPAD/256), Mm)
__global__ __launch_bounds__(256) void k_convA(const float* __restrict__ mle) {
    int k = blockIdx.x * 256 + threadIdx.x;
    int i = blockIdx.y;
    if (k >= KPAD) return;
    float v = 0.f;
    if (k < Vv) v = __expf(mle[(size_t)i * Vv + k]);
    g_A[(size_t)i * KPAD + k] = __float2bfloat16(v);
}

// Wt[d][k] = bf16(W_emb[k][d]) with zero K-padding. 32x32 smem transpose tiles.
// grid: (KPAD/32, Dd/32), block (32, 8)
__global__ __launch_bounds__(256) void k_convW(const float* __restrict__ W) {
    __shared__ float tile[32][33];
    int kb = blockIdx.x * 32, db = blockIdx.y * 32;
    int tx = threadIdx.x, ty = threadIdx.y;
    #pragma unroll
    for (int j = 0; j < 32; j += 8) {
        int k = kb + ty + j;
        tile[ty + j][tx] = (k < Vv) ? W[(size_t)k * Dd + db + tx] : 0.f;
    }
    __syncthreads();
    #pragma unroll
    for (int j = 0; j < 32; j += 8) {
        int d = db + ty + j;
        g_Wt[(size_t)d * KPAD + kb + tx] = __float2bfloat16(tile[tx][ty + j]);
    }
}

// NLL + coverage + dec_len reductions
__global__ __launch_bounds__(256) void k_scalars(
    const float* __restrict__ mle, const float* __restrict__ attn,
    const float* __restrict__ covr, const int* __restrict__ trg,
    const int* __restrict__ dmask, const int* __restrict__ dlen) {
    int tid = threadIdx.x;
    const int NCOV = Bb * LSRC * Tt;
    float s = 0.f;
    for (int idx = blockIdx.x * 256 + tid; idx < NCOV; idx += gridDim.x * 256) {
        int b = idx / (LSRC * Tt);
        int t = idx % Tt;
        float v = fminf(attn[idx], covr[idx]);
        if (dmask[b * Tt + t] != 0) v = 0.f;
        s += v;
    }
    __shared__ float sm[8];
    #pragma unroll
    for (int o = 16; o > 0; o >>= 1) s += __shfl_down_sync(~0u, s, o);
    if ((tid & 31) == 0) sm[tid >> 5] = s;
    __syncthreads();
    if (tid == 0) {
        float tot = 0.f;
        #pragma unroll
        for (int w = 0; w < 8; w++) tot += sm[w];
        atomicAdd(&g_cov, tot);
    }
    if (blockIdx.x == 0) {
        float ls = 0.f, lc = 0.f;
        for (int j = tid; j < Mm; j += 256) {
            int tg = trg[j];
            if (tg != 0) { ls += logf(mle[(size_t)j * Vv + tg]); lc += 1.f; }
        }
        __shared__ float sa[8], sb2[8];
        #pragma unroll
        for (int o = 16; o > 0; o >>= 1) {
            ls += __shfl_down_sync(~0u, ls, o);
            lc += __shfl_down_sync(~0u, lc, o);
        }
        if ((tid & 31) == 0) { sa[tid >> 5] = ls; sb2[tid >> 5] = lc; }
        __syncthreads();
        if (tid == 0) {
            float a = 0.f, b = 0.f;
            #pragma unroll
            for (int w = 0; w < 8; w++) { a += sa[w]; b += sb2[w]; }
            g_nll = a; g_cnt = b;
            g_dec = (float)(dlen[0] + dlen[1] + dlen[2] + dlen[3]);
        }
    }
}

// ---------------- mma.sync GEMM ----------------
// part[z] = A[m0:m0+128, kslice] @ Wt[n0:n0+128, kslice]^T
// grid (4, 4, KSPLIT), 256 threads. Double-buffered smem, cp.async pipeline.
// smem: A0=0, B0=8192, A1=16384, B1=24576 (tiles 128 rows x 64B, SW64 swizzled)
__global__ __launch_bounds__(256) void k_gemm() {
    __shared__ __align__(1024) char smem[32768];
    uint32_t sb = smem_u32(smem);
    int tid = threadIdx.x, l = tid & 31, wid = tid >> 5;
    int wm = wid >> 2, wn = wid & 3;                 // warps: 2(m) x 4(n), warp tile 64x32
    int m0 = blockIdx.x * 128, n0 = blockIdx.y * 128, z = blockIdx.z;
    int it0 = z * SPLIT_ITERS;
    int it1 = min(NKT, it0 + SPLIT_ITERS);

    const __nv_bfloat16* gA = g_A  + (size_t)m0 * KPAD;
    const __nv_bfloat16* gB = g_Wt + (size_t)n0 * KPAD;

    // cp.async: 512 16B-chunks per tile, 2 chunks/thread
    int u0 = tid, u1 = tid + 256;
    int rA0 = u0 >> 2, cA0 = u0 & 3;
    int rA1 = u1 >> 2, cA1 = u1 & 3;
    uint32_t so0 = sw64((uint32_t)(rA0 * 64 + cA0 * 16));
    uint32_t so1 = sw64((uint32_t)(rA1 * 64 + cA1 * 16));

    auto issue = [&](int buf, int it) {
        uint32_t base = sb + buf * 16384;
        size_t k0 = (size_t)it * BK;
        cp_async16(base + so0,        gA + (size_t)rA0 * KPAD + k0 + cA0 * 8);
        cp_async16(base + so1,        gA + (size_t)rA1 * KPAD + k0 + cA1 * 8);
        cp_async16(base + 8192 + so0, gB + (size_t)rA0 * KPAD + k0 + cA0 * 8);
        cp_async16(base + 8192 + so1, gB + (size_t)rA1 * KPAD + k0 + cA1 * 8);
    };

    // ldmatrix per-lane geometry
    int rowA = (l & 15);                      // row within m16 chunk
    int kbA  = (l >> 4) << 4;                 // 0 or 16 bytes (k halves)
    int nB   = (l & 7) + ((l >> 4) << 3);     // n-row within n16 chunk
    int kbB  = ((l >> 3) & 1) << 4;

    float acc[4][4][4];
    #pragma unroll
    for (int a = 0; a < 4; a++)
        #pragma unroll
        for (int b = 0; b < 4; b++)
            #pragma unroll
            for (int c = 0; c < 4; c++) acc[a][b][c] = 0.f;

    issue(0, it0);
    cp_commit();

    for (int it = it0; it < it1; ++it) {
        __syncthreads();                       // previous compute done before buffer reuse
        int buf = (it - it0) & 1;
        if (it + 1 < it1) issue(buf ^ 1, it + 1);
        cp_commit();
        cp_wait1();
        __syncthreads();

        uint32_t baseA = sb + buf * 16384;
        uint32_t baseB = baseA + 8192;
        #pragma unroll
        for (int ks = 0; ks < 2; ks++) {
            uint32_t a[4][4], bfr[2][4];
            #pragma unroll
            for (int mi = 0; mi < 4; mi++) {
                uint32_t off = (uint32_t)((wm * 64 + mi * 16 + rowA) * 64 + ks * 32 + kbA);
                ldm4(a[mi][0], a[mi][1], a[mi][2], a[mi][3], baseA + sw64(off));
            }
            #pragma unroll
            for (int nj = 0; nj < 2; nj++) {
                uint32_t off = (uint32_t)((wn * 32 + nj * 16 + nB) * 64 + ks * 32 + kbB);
                ldm4(bfr[nj][0], bfr[nj][1], bfr[nj][2], bfr[nj][3], baseB + sw64(off));
            }
            #pragma unroll
            for (int mi = 0; mi < 4; mi++)
                #pragma unroll
                for (int nb = 0; nb < 4; nb++)
                    mma16816(acc[mi][nb], a[mi][0], a[mi][1], a[mi][2], a[mi][3],
                             bfr[nb >> 1][2 * (nb & 1)], bfr[nb >> 1][2 * (nb & 1) + 1]);
        }
    }

    // epilogue: write 64x32 warp tile to g_part[z]
    #pragma unroll
    for (int mi = 0; mi < 4; mi++) {
        int r = m0 + wm * 64 + mi * 16 + (l >> 2);
        #pragma unroll
        for (int nb = 0; nb < 4; nb++) {
            int col = n0 + wn * 32 + nb * 8 + 2 * (l & 3);
            float* p0 = g_part + ((size_t)z * Mm + r)     * Dd + col;
            float* p1 = g_part + ((size_t)z * Mm + r + 8) * Dd + col;
            *reinterpret_cast<float2*>(p0) = make_float2(acc[mi][nb][0], acc[mi][nb][1]);
            *reinterpret_cast<float2*>(p1) = make_float2(acc[mi][nb][2], acc[mi][nb][3]);
        }
    }
}

// per-row cosine between pred (summed over ksplit partials) and target embedding
__global__ __launch_bounds__(128) void k_rowcos(const float* __restrict__ W,
                                                const int* __restrict__ trg) {
    int i = blockIdx.x;
    const float* w = W + (size_t)trg[i] * Dd;
    float dot = 0.f, np = 0.f, ne = 0.f;
    for (int d = threadIdx.x; d < Dd; d += 128) {
        float a = 0.f;
        #pragma unroll
        for (int zz = 0; zz < KSPLIT; zz++)
            a += g_part[((size_t)zz * Mm + i) * Dd + d];
        float b = w[d];
        dot += a * b; np += a * a; ne += b * b;
    }
    __shared__ float s0[4], s1[4], s2[4];
    #pragma unroll
    for (int o = 16; o > 0; o >>= 1) {
        dot += __shfl_down_sync(~0u, dot, o);
        np  += __shfl_down_sync(~0u, np,  o);
        ne  += __shfl_down_sync(~0u, ne,  o);
    }
    int wid = threadIdx.x >> 5, lid = threadIdx.x & 31;
    if (lid == 0) { s0[wid] = dot; s1[wid] = np; s2[wid] = ne; }
    __syncthreads();
    if (threadIdx.x == 0) {
        dot = s0[0] + s0[1] + s0[2] + s0[3];
        np  = s1[0] + s1[1] + s1[2] + s1[3];
        ne  = s2[0] + s2[1] + s2[2] + s2[3];
        atomicAdd(&g_cos, dot * rsqrtf(np * ne));
    }
}

__global__ void k_final(float* out) {
    // loss = nll + GAMMA1*cov_loss + GAMMA2 + ot,  ot = trace(C)/n (IPOT fixed point)
    out[0] = (-g_nll / g_cnt) + (g_cov / g_dec) + 0.1f + g_cos * (1.0f / (float)Mm);
}

// ---------------- launch ----------------
extern "C" void kernel_launch(void* const* d_in, const int* in_sizes, int n_in,
                              void* d_out, int out_size) {
    (void)in_sizes; (void)n_in; (void)out_size;
    const float* mle   = (const float*)d_in[0];   // [B, T, V]
    const float* attn  = (const float*)d_in[1];   // [B, LSRC, T]
    const float* covr  = (const float*)d_in[2];   // [B, LSRC, T]
    const int*   trg   = (const int*)  d_in[3];   // [B, T]
    const int*   dmask = (const int*)  d_in[4];   // [B, T]
    const int*   dlen  = (const int*)  d_in[5];   // [B]
    const float* W     = (const float*)d_in[6];   // [V, D]
    float* out = (float*)d_out;

    k_zero<<<1, 1>>>();
    k_convA<<<dim3((KPAD + 255) / 256, Mm), 256>>>(mle);
    k_convW<<<dim3(KPAD / 32, Dd / 32), dim3(32, 8)>>>(W);
    k_scalars<<<256, 256>>>(mle, attn, covr, trg, dmask, dlen);
    k_gemm<<<dim3(4, 4, KSPLIT), 256>>>();
    k_rowcos<<<Mm, 128>>>(W, trg);
    k_final<<<1, 1>>>(out);
}

// round 5
// speedup vs baseline: 1.5225x; 1.5225x over previous
#include <cuda_runtime.h>
#include <cuda_bf16.h>
#include <cstdint>

// ---------------- problem constants ----------------
constexpr int Bb   = 4;
constexpr int Tt   = 128;
constexpr int Vv   = 50257;
constexpr int LSRC = 512;
constexpr int Dd   = 512;
constexpr int Mm   = Bb * Tt;          // 512 rows
constexpr int KPAD = 50304;            // multiple of 128 (>= Vv)
constexpr int BK   = 64;               // fp8 elems per k-tile (64 bytes)
constexpr int NKT  = KPAD / BK;        // 786 k-tiles
constexpr int KSPLIT = 9;
constexpr int SPLIT_ITERS = (NKT + KSPLIT - 1) / KSPLIT;   // 88
constexpr float WSCALE = 256.0f;       // puts W in e4m3 normal range; cancels in cosine

// ---------------- device scratch (no allocs allowed) ----------------
__device__ unsigned char g_A8 [(size_t)Mm * KPAD];   // e4m3(exp(output_mle))
__device__ unsigned char g_Wt8[(size_t)Dd * KPAD];   // e4m3(256 * W_emb^T) [D, K]
__device__ float g_part[(size_t)KSPLIT * Mm * Dd];   // per-ksplit GEMM partials
__device__ float g_cov, g_nll, g_cnt, g_cos, g_dec;

// ---------------- helpers ----------------
__device__ __forceinline__ uint32_t smem_u32(const void* p) {
    return (uint32_t)__cvta_generic_to_shared(p);
}
__device__ __forceinline__ uint32_t sw64(uint32_t x) {      // SW64 swizzle for 64B rows
    return x ^ ((x >> 3) & 0x30);
}
__device__ __forceinline__ void cp_async16(uint32_t saddr, const void* gaddr) {
    asm volatile("cp.async.cg.shared.global [%0], [%1], 16;" :: "r"(saddr), "l"(gaddr));
}
__device__ __forceinline__ void cp_commit() {
    asm volatile("cp.async.commit_group;" ::: "memory");
}
__device__ __forceinline__ void cp_wait1() {
    asm volatile("cp.async.wait_group 1;" ::: "memory");
}
__device__ __forceinline__ void ldm4(uint32_t& r0, uint32_t& r1, uint32_t& r2, uint32_t& r3,
                                     uint32_t addr) {
    asm volatile("ldmatrix.sync.aligned.m8n8.x4.shared.b16 {%0,%1,%2,%3}, [%4];"
                 : "=r"(r0), "=r"(r1), "=r"(r2), "=r"(r3) : "r"(addr));
}
// fp8 e4m3 MMA: byte-layout-compatible with the bf16 m16n8k16 fragments
__device__ __forceinline__ void mma16832(float* c, uint32_t a0, uint32_t a1, uint32_t a2,
                                         uint32_t a3, uint32_t b0, uint32_t b1) {
    asm volatile("mma.sync.aligned.m16n8k32.row.col.f32.e4m3.e4m3.f32 "
                 "{%0,%1,%2,%3}, {%4,%5,%6,%7}, {%8,%9}, {%0,%1,%2,%3};"
                 : "+f"(c[0]), "+f"(c[1]), "+f"(c[2]), "+f"(c[3])
                 : "r"(a0), "r"(a1), "r"(a2), "r"(a3), "r"(b0), "r"(b1));
}
// pack two floats -> two e4m3 bytes (hi<<8 | lo)
__device__ __forceinline__ uint32_t f2e4m3x2(float hi, float lo) {
    uint32_t u;
    asm("{\n\t.reg .b16 t;\n\tcvt.rn.satfinite.e4m3x2.f32 t, %1, %2;\n\t"
        "cvt.u32.u16 %0, t;\n\t}" : "=r"(u) : "f"(hi), "f"(lo));
    return u;
}

// ---------------- kernels ----------------
// A = e4m3(exp(output_mle)), zero K-padding. Also zeroes scalar accumulators.
// grid: (KPAD/4/256 rounded up, Mm), 4 elems/thread -> one uint store
__global__ __launch_bounds__(256) void k_convA(const float* __restrict__ mle) {
    if (blockIdx.x == 0 && blockIdx.y == 0 && threadIdx.x == 0) {
        g_cov = 0.f; g_nll = 0.f; g_cnt = 0.f; g_cos = 0.f;
    }
    int k4 = (blockIdx.x * 256 + threadIdx.x) * 4;
    int i = blockIdx.y;
    if (k4 >= KPAD) return;
    const float* row = mle + (size_t)i * Vv;
    float v[4];
    #pragma unroll
    for (int j = 0; j < 4; j++) {
        int k = k4 + j;
        v[j] = (k < Vv) ? __expf(row[k]) : 0.f;
    }
    uint32_t lo = f2e4m3x2(v[1], v[0]);
    uint32_t hi = f2e4m3x2(v[3], v[2]);
    *reinterpret_cast<uint32_t*>(g_A8 + (size_t)i * KPAD + k4) = lo | (hi << 16);
}

// Wt[d][k] = e4m3(256 * W[k][d]), zero K-padding.
// grid: (KPAD/128, Dd/32), 256 threads. smem transpose tile 128(k) x 32(d).
__global__ __launch_bounds__(256) void k_convW(const float* __restrict__ W) {
    __shared__ float tile[128][33];
    int kb = blockIdx.x * 128, db = blockIdx.y * 32;
    int t = threadIdx.x;
    // load: 2 threads per k-row, 16 floats each (4x float4)
    {
        int krow = t >> 1, dseg = (t & 1) * 16;
        int k = kb + krow;
        if (k < Vv) {
            const float4* src = reinterpret_cast<const float4*>(W + (size_t)k * Dd + db + dseg);
            #pragma unroll
            for (int j = 0; j < 4; j++) {
                float4 f = src[j];
                tile[krow][dseg + j * 4 + 0] = f.x;
                tile[krow][dseg + j * 4 + 1] = f.y;
                tile[krow][dseg + j * 4 + 2] = f.z;
                tile[krow][dseg + j * 4 + 3] = f.w;
            }
        } else {
            #pragma unroll
            for (int j = 0; j < 16; j++) tile[krow][dseg + j] = 0.f;
        }
    }
    __syncthreads();
    // store: one thread per (d, 16k) chunk -> uint4 of fp8
    {
        int dl = t >> 3, kseg = (t & 7) * 16;
        uint32_t w[4];
        #pragma unroll
        for (int q = 0; q < 4; q++) {
            float a = tile[kseg + q * 4 + 0][dl] * WSCALE;
            float b = tile[kseg + q * 4 + 1][dl] * WSCALE;
            float c = tile[kseg + q * 4 + 2][dl] * WSCALE;
            float d = tile[kseg + q * 4 + 3][dl] * WSCALE;
            w[q] = f2e4m3x2(b, a) | (f2e4m3x2(d, c) << 16);
        }
        uint4 out = make_uint4(w[0], w[1], w[2], w[3]);
        *reinterpret_cast<uint4*>(g_Wt8 + (size_t)(db + dl) * KPAD + kb + kseg) = out;
    }
}

// NLL + coverage + dec_len reductions (vectorized coverage loads)
__global__ __launch_bounds__(256) void k_scalars(
    const float* __restrict__ mle, const float* __restrict__ attn,
    const float* __restrict__ covr, const int* __restrict__ trg,
    const int* __restrict__ dmask, const int* __restrict__ dlen) {
    int tid = threadIdx.x;
    const int NCOV4 = Bb * LSRC * Tt / 4;   // 65536 float4s, exactly gridDim*blockDim
    float s = 0.f;
    {
        int idx4 = blockIdx.x * 256 + tid;
        if (idx4 < NCOV4) {
            int g = idx4 * 4;
            int b = g / (LSRC * Tt);
            int t0 = g & (Tt - 1);          // Tt=128 power of 2
            float4 a = reinterpret_cast<const float4*>(attn)[idx4];
            float4 c = reinterpret_cast<const float4*>(covr)[idx4];
            const int* mrow = dmask + b * Tt;
            float m0 = mrow[t0]     ? 0.f : 1.f;
            float m1 = mrow[t0 + 1] ? 0.f : 1.f;
            float m2 = mrow[t0 + 2] ? 0.f : 1.f;
            float m3 = mrow[t0 + 3] ? 0.f : 1.f;
            s = fminf(a.x, c.x) * m0 + fminf(a.y, c.y) * m1 +
                fminf(a.z, c.z) * m2 + fminf(a.w, c.w) * m3;
        }
    }
    __shared__ float sm[8];
    #pragma unroll
    for (int o = 16; o > 0; o >>= 1) s += __shfl_down_sync(~0u, s, o);
    if ((tid & 31) == 0) sm[tid >> 5] = s;
    __syncthreads();
    if (tid == 0) {
        float tot = 0.f;
        #pragma unroll
        for (int w = 0; w < 8; w++) tot += sm[w];
        atomicAdd(&g_cov, tot);
    }
    if (blockIdx.x == 0) {
        float ls = 0.f, lc = 0.f;
        for (int j = tid; j < Mm; j += 256) {
            int tg = trg[j];
            if (tg != 0) { ls += logf(mle[(size_t)j * Vv + tg]); lc += 1.f; }
        }
        __shared__ float sa[8], sb2[8];
        #pragma unroll
        for (int o = 16; o > 0; o >>= 1) {
            ls += __shfl_down_sync(~0u, ls, o);
            lc += __shfl_down_sync(~0u, lc, o);
        }
        if ((tid & 31) == 0) { sa[tid >> 5] = ls; sb2[tid >> 5] = lc; }
        __syncthreads();
        if (tid == 0) {
            float a = 0.f, b = 0.f;
            #pragma unroll
            for (int w = 0; w < 8; w++) { a += sa[w]; b += sb2[w]; }
            g_nll = a; g_cnt = b;
            g_dec = (float)(dlen[0] + dlen[1] + dlen[2] + dlen[3]);
        }
    }
}

// ---------------- fp8 mma.sync GEMM ----------------
// part[z] = A[m0:m0+128, kslice] @ Wt[n0:n0+128, kslice]^T   (e4m3 x e4m3 -> f32)
// grid (4, 4, KSPLIT), 256 threads. Double-buffered smem, cp.async pipeline.
// smem: A0=0, B0=8192, A1=16384, B1=24576 (tiles 128 rows x 64B, SW64 swizzled)
__global__ __launch_bounds__(256) void k_gemm() {
    __shared__ __align__(1024) char smem[32768];
    uint32_t sb = smem_u32(smem);
    int tid = threadIdx.x, l = tid & 31, wid = tid >> 5;
    int wm = wid >> 2, wn = wid & 3;                 // warps: 2(m) x 4(n), warp tile 64x32
    int m0 = blockIdx.x * 128, n0 = blockIdx.y * 128, z = blockIdx.z;
    int it0 = z * SPLIT_ITERS;
    int it1 = min(NKT, it0 + SPLIT_ITERS);

    const unsigned char* gA = g_A8  + (size_t)m0 * KPAD;
    const unsigned char* gB = g_Wt8 + (size_t)n0 * KPAD;

    // cp.async: 512 16B-chunks per tile, 2 chunks/thread
    int u0 = tid, u1 = tid + 256;
    int rA0 = u0 >> 2, cA0 = u0 & 3;
    int rA1 = u1 >> 2, cA1 = u1 & 3;
    uint32_t so0 = sw64((uint32_t)(rA0 * 64 + cA0 * 16));
    uint32_t so1 = sw64((uint32_t)(rA1 * 64 + cA1 * 16));

    auto issue = [&](int buf, int it) {
        uint32_t base = sb + buf * 16384;
        size_t k0 = (size_t)it * BK;                 // byte offset (1 B/elem)
        cp_async16(base + so0,        gA + (size_t)rA0 * KPAD + k0 + cA0 * 16);
        cp_async16(base + so1,        gA + (size_t)rA1 * KPAD + k0 + cA1 * 16);
        cp_async16(base + 8192 + so0, gB + (size_t)rA0 * KPAD + k0 + cA0 * 16);
        cp_async16(base + 8192 + so1, gB + (size_t)rA1 * KPAD + k0 + cA1 * 16);
    };

    // ldmatrix per-lane geometry (byte-identical to the proven bf16 layout)
    int rowA = (l & 15);
    int kbA  = (l >> 4) << 4;
    int nB   = (l & 7) + ((l >> 4) << 3);
    int kbB  = ((l >> 3) & 1) << 4;

    float acc[4][4][4];
    #pragma unroll
    for (int a = 0; a < 4; a++)
        #pragma unroll
        for (int b = 0; b < 4; b++)
            #pragma unroll
            for (int c = 0; c < 4; c++) acc[a][b][c] = 0.f;

    issue(0, it0);
    cp_commit();

    for (int it = it0; it < it1; ++it) {
        __syncthreads();                       // previous compute done before buffer reuse
        int buf = (it - it0) & 1;
        if (it + 1 < it1) issue(buf ^ 1, it + 1);
        cp_commit();
        cp_wait1();
        __syncthreads();

        uint32_t baseA = sb + buf * 16384;
        uint32_t baseB = baseA + 8192;
        #pragma unroll
        for (int ks = 0; ks < 2; ks++) {       // two 32-byte k-halves (k=32 fp8 each)
            uint32_t a[4][4], bfr[2][4];
            #pragma unroll
            for (int mi = 0; mi < 4; mi++) {
                uint32_t off = (uint32_t)((wm * 64 + mi * 16 + rowA) * 64 + ks * 32 + kbA);
                ldm4(a[mi][0], a[mi][1], a[mi][2], a[mi][3], baseA + sw64(off));
            }
            #pragma unroll
            for (int nj = 0; nj < 2; nj++) {
                uint32_t off = (uint32_t)((wn * 32 + nj * 16 + nB) * 64 + ks * 32 + kbB);
                ldm4(bfr[nj][0], bfr[nj][1], bfr[nj][2], bfr[nj][3], baseB + sw64(off));
            }
            #pragma unroll
            for (int mi = 0; mi < 4; mi++)
                #pragma unroll
                for (int nb = 0; nb < 4; nb++)
                    mma16832(acc[mi][nb], a[mi][0], a[mi][1], a[mi][2], a[mi][3],
                             bfr[nb >> 1][2 * (nb & 1)], bfr[nb >> 1][2 * (nb & 1) + 1]);
        }
    }

    // epilogue: write 64x32 warp tile to g_part[z]
    #pragma unroll
    for (int mi = 0; mi < 4; mi++) {
        int r = m0 + wm * 64 + mi * 16 + (l >> 2);
        #pragma unroll
        for (int nb = 0; nb < 4; nb++) {
            int col = n0 + wn * 32 + nb * 8 + 2 * (l & 3);
            float* p0 = g_part + ((size_t)z * Mm + r)     * Dd + col;
            float* p1 = g_part + ((size_t)z * Mm + r + 8) * Dd + col;
            *reinterpret_cast<float2*>(p0) = make_float2(acc[mi][nb][0], acc[mi][nb][1]);
            *reinterpret_cast<float2*>(p1) = make_float2(acc[mi][nb][2], acc[mi][nb][3]);
        }
    }
}

// per-row cosine between pred (summed over ksplit partials) and target embedding
__global__ __launch_bounds__(128) void k_rowcos(const float* __restrict__ W,
                                                const int* __restrict__ trg) {
    int i = blockIdx.x;
    const float4* w4 = reinterpret_cast<const float4*>(W + (size_t)trg[i] * Dd);
    float dot = 0.f, np = 0.f, ne = 0.f;
    {
        int d4 = threadIdx.x;                  // Dd/4 = 128 = blockDim
        float4 a = make_float4(0.f, 0.f, 0.f, 0.f);
        #pragma unroll
        for (int zz = 0; zz < KSPLIT; zz++) {
            float4 p = reinterpret_cast<const float4*>(
                g_part + ((size_t)zz * Mm + i) * Dd)[d4];
            a.x += p.x; a.y += p.y; a.z += p.z; a.w += p.w;
        }
        float4 b = w4[d4];
        dot = a.x * b.x + a.y * b.y + a.z * b.z + a.w * b.w;
        np  = a.x * a.x + a.y * a.y + a.z * a.z + a.w * a.w;
        ne  = b.x * b.x + b.y * b.y + b.z * b.z + b.w * b.w;
    }
    __shared__ float s0[4], s1[4], s2[4];
    #pragma unroll
    for (int o = 16; o > 0; o >>= 1) {
        dot += __shfl_down_sync(~0u, dot, o);
        np  += __shfl_down_sync(~0u, np,  o);
        ne  += __shfl_down_sync(~0u, ne,  o);
    }
    int wid = threadIdx.x >> 5, lid = threadIdx.x & 31;
    if (lid == 0) { s0[wid] = dot; s1[wid] = np; s2[wid] = ne; }
    __syncthreads();
    if (threadIdx.x == 0) {
        dot = s0[0] + s0[1] + s0[2] + s0[3];
        np  = s1[0] + s1[1] + s1[2] + s1[3];
        ne  = s2[0] + s2[1] + s2[2] + s2[3];
        atomicAdd(&g_cos, dot * rsqrtf(np * ne));
    }
}

__global__ void k_final(float* out) {
    // loss = nll + GAMMA1*cov_loss + GAMMA2 + ot,  ot = trace(C)/n (IPOT fixed point)
    out[0] = (-g_nll / g_cnt) + (g_cov / g_dec) + 0.1f + g_cos * (1.0f / (float)Mm);
}

// ---------------- launch ----------------
extern "C" void kernel_launch(void* const* d_in, const int* in_sizes, int n_in,
                              void* d_out, int out_size) {
    (void)in_sizes; (void)n_in; (void)out_size;
    const float* mle   = (const float*)d_in[0];   // [B, T, V]
    const float* attn  = (const float*)d_in[1];   // [B, LSRC, T]
    const float* covr  = (const float*)d_in[2];   // [B, LSRC, T]
    const int*   trg   = (const int*)  d_in[3];   // [B, T]
    const int*   dmask = (const int*)  d_in[4];   // [B, T]
    const int*   dlen  = (const int*)  d_in[5];   // [B]
    const float* W     = (const float*)d_in[6];   // [V, D]
    float* out = (float*)d_out;

    k_convA<<<dim3((KPAD / 4 + 255) / 256, Mm), 256>>>(mle);
    k_convW<<<dim3(KPAD / 128, Dd / 32), 256>>>(W);
    k_scalars<<<256, 256>>>(mle, attn, covr, trg, dmask, dlen);
    k_gemm<<<dim3(4, 4, KSPLIT), 256>>>();
    k_rowcos<<<Mm, 128>>>(W, trg);
    k_final<<<1, 1>>>(out);
}

// round 6
// speedup vs baseline: 1.6626x; 1.0920x over previous
#include <cuda_runtime.h>
#include <cuda_bf16.h>
#include <cstdint>

// ---------------- problem constants ----------------
constexpr int Bb   = 4;
constexpr int Tt   = 128;
constexpr int Vv   = 50257;
constexpr int LSRC = 512;
constexpr int Dd   = 512;
constexpr int Mm   = Bb * Tt;          // 512 rows
constexpr int KPAD = 50304;            // multiple of 128 (>= Vv)
constexpr int BK   = 128;              // fp8 elems (bytes) per k-tile
constexpr int NKT  = KPAD / BK;        // 393 k-tiles
constexpr int KSPLIT = 9;
constexpr int SPLIT_ITERS = (NKT + KSPLIT - 1) / KSPLIT;   // 44
constexpr float WSCALE = 256.0f;       // puts W in e4m3 normal range; cancels in cosine

constexpr int STAGE = 32768;           // A tile 16KB + B tile 16KB
constexpr int GEMM_SMEM = 3 * STAGE + 1024;   // +pad for 1024-alignment

// ---------------- device scratch (no allocs allowed) ----------------
__device__ unsigned char g_A8 [(size_t)Mm * KPAD];   // e4m3(exp(output_mle))
__device__ unsigned char g_Wt8[(size_t)Dd * KPAD];   // e4m3(256 * W_emb^T) [D, K]
__device__ float g_part[(size_t)KSPLIT * Mm * Dd];   // per-ksplit GEMM partials
__device__ float g_cov, g_nll, g_cnt, g_cos, g_dec;

// ---------------- helpers ----------------
__device__ __forceinline__ uint32_t smem_u32(const void* p) {
    return (uint32_t)__cvta_generic_to_shared(p);
}
__device__ __forceinline__ uint32_t sw128(uint32_t x) {     // SW128 for 128B rows
    return x ^ ((x >> 3) & 0x70);
}
__device__ __forceinline__ void cp_async16(uint32_t saddr, const void* gaddr) {
    asm volatile("cp.async.cg.shared.global [%0], [%1], 16;" :: "r"(saddr), "l"(gaddr));
}
__device__ __forceinline__ void cp_commit() {
    asm volatile("cp.async.commit_group;" ::: "memory");
}
__device__ __forceinline__ void cp_wait1() {
    asm volatile("cp.async.wait_group 1;" ::: "memory");
}
__device__ __forceinline__ void ldm4(uint32_t& r0, uint32_t& r1, uint32_t& r2, uint32_t& r3,
                                     uint32_t addr) {
    asm volatile("ldmatrix.sync.aligned.m8n8.x4.shared.b16 {%0,%1,%2,%3}, [%4];"
                 : "=r"(r0), "=r"(r1), "=r"(r2), "=r"(r3) : "r"(addr));
}
__device__ __forceinline__ void mma16832(float* c, uint32_t a0, uint32_t a1, uint32_t a2,
                                         uint32_t a3, uint32_t b0, uint32_t b1) {
    asm volatile("mma.sync.aligned.m16n8k32.row.col.f32.e4m3.e4m3.f32 "
                 "{%0,%1,%2,%3}, {%4,%5,%6,%7}, {%8,%9}, {%0,%1,%2,%3};"
                 : "+f"(c[0]), "+f"(c[1]), "+f"(c[2]), "+f"(c[3])
                 : "r"(a0), "r"(a1), "r"(a2), "r"(a3), "r"(b0), "r"(b1));
}
__device__ __forceinline__ uint32_t f2e4m3x2(float hi, float lo) {
    uint32_t u;
    asm("{\n\t.reg .b16 t;\n\tcvt.rn.satfinite.e4m3x2.f32 t, %1, %2;\n\t"
        "cvt.u32.u16 %0, t;\n\t}" : "=r"(u) : "f"(hi), "f"(lo));
    return u;
}

// ---------------- kernels ----------------
// A = e4m3(exp(output_mle)), zero K-padding. Also zeroes scalar accumulators.
__global__ __launch_bounds__(256) void k_convA(const float* __restrict__ mle) {
    if (blockIdx.x == 0 && blockIdx.y == 0 && threadIdx.x == 0) {
        g_cov = 0.f; g_nll = 0.f; g_cnt = 0.f; g_cos = 0.f;
    }
    int k4 = (blockIdx.x * 256 + threadIdx.x) * 4;
    int i = blockIdx.y;
    if (k4 >= KPAD) return;
    const float* row = mle + (size_t)i * Vv;
    float v[4];
    #pragma unroll
    for (int j = 0; j < 4; j++) {
        int k = k4 + j;
        v[j] = (k < Vv) ? __expf(row[k]) : 0.f;
    }
    uint32_t lo = f2e4m3x2(v[1], v[0]);
    uint32_t hi = f2e4m3x2(v[3], v[2]);
    *reinterpret_cast<uint32_t*>(g_A8 + (size_t)i * KPAD + k4) = lo | (hi << 16);
}

// Wt[d][k] = e4m3(256 * W[k][d]), zero K-padding. smem transpose tile 128(k) x 32(d).
__global__ __launch_bounds__(256) void k_convW(const float* __restrict__ W) {
    __shared__ float tile[128][33];
    int kb = blockIdx.x * 128, db = blockIdx.y * 32;
    int t = threadIdx.x;
    {
        int krow = t >> 1, dseg = (t & 1) * 16;
        int k = kb + krow;
        if (k < Vv) {
            const float4* src = reinterpret_cast<const float4*>(W + (size_t)k * Dd + db + dseg);
            #pragma unroll
            for (int j = 0; j < 4; j++) {
                float4 f = src[j];
                tile[krow][dseg + j * 4 + 0] = f.x;
                tile[krow][dseg + j * 4 + 1] = f.y;
                tile[krow][dseg + j * 4 + 2] = f.z;
                tile[krow][dseg + j * 4 + 3] = f.w;
            }
        } else {
            #pragma unroll
            for (int j = 0; j < 16; j++) tile[krow][dseg + j] = 0.f;
        }
    }
    __syncthreads();
    {
        int dl = t >> 3, kseg = (t & 7) * 16;
        uint32_t w[4];
        #pragma unroll
        for (int q = 0; q < 4; q++) {
            float a = tile[kseg + q * 4 + 0][dl] * WSCALE;
            float b = tile[kseg + q * 4 + 1][dl] * WSCALE;
            float c = tile[kseg + q * 4 + 2][dl] * WSCALE;
            float d = tile[kseg + q * 4 + 3][dl] * WSCALE;
            w[q] = f2e4m3x2(b, a) | (f2e4m3x2(d, c) << 16);
        }
        uint4 out = make_uint4(w[0], w[1], w[2], w[3]);
        *reinterpret_cast<uint4*>(g_Wt8 + (size_t)(db + dl) * KPAD + kb + kseg) = out;
    }
}

// NLL + coverage + dec_len reductions
__global__ __launch_bounds__(256) void k_scalars(
    const float* __restrict__ mle, const float* __restrict__ attn,
    const float* __restrict__ covr, const int* __restrict__ trg,
    const int* __restrict__ dmask, const int* __restrict__ dlen) {
    int tid = threadIdx.x;
    const int NCOV4 = Bb * LSRC * Tt / 4;
    float s = 0.f;
    {
        int idx4 = blockIdx.x * 256 + tid;
        if (idx4 < NCOV4) {
            int g = idx4 * 4;
            int b = g / (LSRC * Tt);
            int t0 = g & (Tt - 1);
            float4 a = reinterpret_cast<const float4*>(attn)[idx4];
            float4 c = reinterpret_cast<const float4*>(covr)[idx4];
            const int* mrow = dmask + b * Tt;
            float m0 = mrow[t0]     ? 0.f : 1.f;
            float m1 = mrow[t0 + 1] ? 0.f : 1.f;
            float m2 = mrow[t0 + 2] ? 0.f : 1.f;
            float m3 = mrow[t0 + 3] ? 0.f : 1.f;
            s = fminf(a.x, c.x) * m0 + fminf(a.y, c.y) * m1 +
                fminf(a.z, c.z) * m2 + fminf(a.w, c.w) * m3;
        }
    }
    __shared__ float sm[8];
    #pragma unroll
    for (int o = 16; o > 0; o >>= 1) s += __shfl_down_sync(~0u, s, o);
    if ((tid & 31) == 0) sm[tid >> 5] = s;
    __syncthreads();
    if (tid == 0) {
        float tot = 0.f;
        #pragma unroll
        for (int w = 0; w < 8; w++) tot += sm[w];
        atomicAdd(&g_cov, tot);
    }
    if (blockIdx.x == 0) {
        float ls = 0.f, lc = 0.f;
        for (int j = tid; j < Mm; j += 256) {
            int tg = trg[j];
            if (tg != 0) { ls += logf(mle[(size_t)j * Vv + tg]); lc += 1.f; }
        }
        __shared__ float sa[8], sb2[8];
        #pragma unroll
        for (int o = 16; o > 0; o >>= 1) {
            ls += __shfl_down_sync(~0u, ls, o);
            lc += __shfl_down_sync(~0u, lc, o);
        }
        if ((tid & 31) == 0) { sa[tid >> 5] = ls; sb2[tid >> 5] = lc; }
        __syncthreads();
        if (tid == 0) {
            float a = 0.f, b = 0.f;
            #pragma unroll
            for (int w = 0; w < 8; w++) { a += sa[w]; b += sb2[w]; }
            g_nll = a; g_cnt = b;
            g_dec = (float)(dlen[0] + dlen[1] + dlen[2] + dlen[3]);
        }
    }
}

// ---------------- fp8 mma.sync GEMM ----------------
// part[z] = A[m0:m0+128, kslice] @ Wt[n0:n0+128, kslice]^T   (e4m3 x e4m3 -> f32)
// grid (4, 4, KSPLIT), 256 threads. 3-stage cp.async pipeline, BK=128B,
// SW128 smem (128B rows), ONE __syncthreads per k-iteration.
__global__ __launch_bounds__(256) void k_gemm() {
    extern __shared__ char dsm[];
    uint32_t sb = (smem_u32(dsm) + 1023) & ~1023u;     // 1024-align for SW128
    int tid = threadIdx.x, l = tid & 31, wid = tid >> 5;
    int wm = wid >> 2, wn = wid & 3;                   // warps: 2(m) x 4(n), tile 64x32
    int m0 = blockIdx.x * 128, n0 = blockIdx.y * 128, z = blockIdx.z;
    int it0 = z * SPLIT_ITERS;
    int it1 = min(NKT, it0 + SPLIT_ITERS);
    int niter = it1 - it0;

    const unsigned char* gA = g_A8  + (size_t)m0 * KPAD;
    const unsigned char* gB = g_Wt8 + (size_t)n0 * KPAD;

    // cp.async geometry: 1024 16B-chunks per operand tile, 4 per thread
    // u = tid + i*256 ; row = u>>3 ; c = u&7
    uint32_t so[4];
    const unsigned char* pA[4];
    const unsigned char* pB[4];
    #pragma unroll
    for (int i = 0; i < 4; i++) {
        int u = tid + i * 256;
        int row = u >> 3, c = u & 7;
        so[i] = sw128((uint32_t)(row * 128 + c * 16));
        pA[i] = gA + (size_t)row * KPAD + (size_t)it0 * BK + c * 16;
        pB[i] = gB + (size_t)row * KPAD + (size_t)it0 * BK + c * 16;
    }

    auto issue = [&](int buf, int step) {       // step = iterations ahead of it0
        uint32_t base = sb + buf * STAGE;
        size_t koff = (size_t)step * BK;
        #pragma unroll
        for (int i = 0; i < 4; i++) {
            cp_async16(base + so[i],         pA[i] + koff);
            cp_async16(base + 16384 + so[i], pB[i] + koff);
        }
    };

    // hoisted swizzled ldmatrix addresses (per-thread constants within a buffer)
    int rowA = (l & 15);
    int kbA  = (l >> 4) << 4;
    int nB   = (l & 7) + ((l >> 4) << 3);
    int kbB  = ((l >> 3) & 1) << 4;
    uint32_t swA[4][4], swB[2][4];
    #pragma unroll
    for (int mi = 0; mi < 4; mi++)
        #pragma unroll
        for (int ks = 0; ks < 4; ks++)
            swA[mi][ks] = sw128((uint32_t)((wm * 64 + mi * 16 + rowA) * 128 + ks * 32 + kbA));
    #pragma unroll
    for (int nj = 0; nj < 2; nj++)
        #pragma unroll
        for (int ks = 0; ks < 4; ks++)
            swB[nj][ks] = sw128((uint32_t)((wn * 32 + nj * 16 + nB) * 128 + ks * 32 + kbB)
                                + 16384u);

    float acc[4][4][4];
    #pragma unroll
    for (int a = 0; a < 4; a++)
        #pragma unroll
        for (int b = 0; b < 4; b++)
            #pragma unroll
            for (int c = 0; c < 4; c++) acc[a][b][c] = 0.f;

    issue(0, 0); cp_commit();
    if (niter > 1) issue(1, 1);
    cp_commit();

    for (int s = 0; s < niter; ++s) {
        cp_wait1();
        __syncthreads();                       // stage s ready; compute s-1 done by all
        if (s + 2 < niter) issue((s + 2) % 3, s + 2);
        cp_commit();

        uint32_t base = sb + (s % 3) * STAGE;
        #pragma unroll
        for (int ks = 0; ks < 4; ks++) {
            uint32_t a[4][4], bfr[2][4];
            #pragma unroll
            for (int mi = 0; mi < 4; mi++)
                ldm4(a[mi][0], a[mi][1], a[mi][2], a[mi][3], base + swA[mi][ks]);
            #pragma unroll
            for (int nj = 0; nj < 2; nj++)
                ldm4(bfr[nj][0], bfr[nj][1], bfr[nj][2], bfr[nj][3], base + swB[nj][ks]);
            #pragma unroll
            for (int mi = 0; mi < 4; mi++)
                #pragma unroll
                for (int nb = 0; nb < 4; nb++)
                    mma16832(acc[mi][nb], a[mi][0], a[mi][1], a[mi][2], a[mi][3],
                             bfr[nb >> 1][2 * (nb & 1)], bfr[nb >> 1][2 * (nb & 1) + 1]);
        }
    }

    // epilogue: write 64x32 warp tile to g_part[z]
    #pragma unroll
    for (int mi = 0; mi < 4; mi++) {
        int r = m0 + wm * 64 + mi * 16 + (l >> 2);
        #pragma unroll
        for (int nb = 0; nb < 4; nb++) {
            int col = n0 + wn * 32 + nb * 8 + 2 * (l & 3);
            float* p0 = g_part + ((size_t)z * Mm + r)     * Dd + col;
            float* p1 = g_part + ((size_t)z * Mm + r + 8) * Dd + col;
            *reinterpret_cast<float2*>(p0) = make_float2(acc[mi][nb][0], acc[mi][nb][1]);
            *reinterpret_cast<float2*>(p1) = make_float2(acc[mi][nb][2], acc[mi][nb][3]);
        }
    }
}

// per-row cosine between pred (summed over ksplit partials) and target embedding
__global__ __launch_bounds__(128) void k_rowcos(const float* __restrict__ W,
                                                const int* __restrict__ trg) {
    int i = blockIdx.x;
    const float4* w4 = reinterpret_cast<const float4*>(W + (size_t)trg[i] * Dd);
    float dot = 0.f, np = 0.f, ne = 0.f;
    {
        int d4 = threadIdx.x;                  // Dd/4 = 128 = blockDim
        float4 a = make_float4(0.f, 0.f, 0.f, 0.f);
        #pragma unroll
        for (int zz = 0; zz < KSPLIT; zz++) {
            float4 p = reinterpret_cast<const float4*>(
                g_part + ((size_t)zz * Mm + i) * Dd)[d4];
            a.x += p.x; a.y += p.y; a.z += p.z; a.w += p.w;
        }
        float4 b = w4[d4];
        dot = a.x * b.x + a.y * b.y + a.z * b.z + a.w * b.w;
        np  = a.x * a.x + a.y * a.y + a.z * a.z + a.w * a.w;
        ne  = b.x * b.x + b.y * b.y + b.z * b.z + b.w * b.w;
    }
    __shared__ float s0[4], s1[4], s2[4];
    #pragma unroll
    for (int o = 16; o > 0; o >>= 1) {
        dot += __shfl_down_sync(~0u, dot, o);
        np  += __shfl_down_sync(~0u, np,  o);
        ne  += __shfl_down_sync(~0u, ne,  o);
    }
    int wid = threadIdx.x >> 5, lid = threadIdx.x & 31;
    if (lid == 0) { s0[wid] = dot; s1[wid] = np; s2[wid] = ne; }
    __syncthreads();
    if (threadIdx.x == 0) {
        dot = s0[0] + s0[1] + s0[2] + s0[3];
        np  = s1[0] + s1[1] + s1[2] + s1[3];
        ne  = s2[0] + s2[1] + s2[2] + s2[3];
        atomicAdd(&g_cos, dot * rsqrtf(np * ne));
    }
}

__global__ void k_final(float* out) {
    // loss = nll + GAMMA1*cov_loss + GAMMA2 + ot,  ot = trace(C)/n (IPOT fixed point)
    out[0] = (-g_nll / g_cnt) + (g_cov / g_dec) + 0.1f + g_cos * (1.0f / (float)Mm);
}

// ---------------- launch ----------------
extern "C" void kernel_launch(void* const* d_in, const int* in_sizes, int n_in,
                              void* d_out, int out_size) {
    (void)in_sizes; (void)n_in; (void)out_size;
    const float* mle   = (const float*)d_in[0];   // [B, T, V]
    const float* attn  = (const float*)d_in[1];   // [B, LSRC, T]
    const float* covr  = (const float*)d_in[2];   // [B, LSRC, T]
    const int*   trg   = (const int*)  d_in[3];   // [B, T]
    const int*   dmask = (const int*)  d_in[4];   // [B, T]
    const int*   dlen  = (const int*)  d_in[5];   // [B]
    const float* W     = (const float*)d_in[6];   // [V, D]
    float* out = (float*)d_out;

    cudaFuncSetAttribute(k_gemm, cudaFuncAttributeMaxDynamicSharedMemorySize, GEMM_SMEM);

    k_convA<<<dim3((KPAD / 4 + 255) / 256, Mm), 256>>>(mle);
    k_convW<<<dim3(KPAD / 128, Dd / 32), 256>>>(W);
    k_scalars<<<256, 256>>>(mle, attn, covr, trg, dmask, dlen);
    k_gemm<<<dim3(4, 4, KSPLIT), 256, GEMM_SMEM>>>();
    k_rowcos<<<Mm, 128>>>(W, trg);
    k_final<<<1, 1>>>(out);
}

// round 10
// speedup vs baseline: 1.6891x; 1.0159x over previous
#include <cuda_runtime.h>
#include <cuda_bf16.h>
#include <cstdint>

// ---------------- problem constants ----------------
constexpr int Bb   = 4;
constexpr int Tt   = 128;
constexpr int Vv   = 50257;
constexpr int LSRC = 512;
constexpr int Dd   = 512;
constexpr int Mm   = Bb * Tt;          // 512 rows
constexpr int KPAD = 50304;            // multiple of 128 (>= Vv)
constexpr int BK   = 128;              // fp8 elems (bytes) per k-tile
constexpr int NKT  = KPAD / BK;        // 393 k-tiles
constexpr int KSPLIT = 9;
constexpr int SPLIT_ITERS = (NKT + KSPLIT - 1) / KSPLIT;   // 44
constexpr float WSCALE = 256.0f;       // puts W in e4m3 normal range; cancels in cosine

constexpr int STAGE = 32768;           // A tile 16KB + B tile 16KB
constexpr int GEMM_SMEM = 3 * STAGE + 1024;   // +pad for 1024-alignment

// ---------------- device scratch (no allocs allowed) ----------------
__device__ unsigned char g_A8 [(size_t)Mm * KPAD];   // e4m3(exp(output_mle))
__device__ unsigned char g_Wt8[(size_t)Dd * KPAD];   // e4m3(256 * W_emb^T) [D, K]
__device__ float g_part[(size_t)KSPLIT * Mm * Dd];   // per-ksplit GEMM partials
__device__ float g_cov, g_nll, g_cnt, g_cos, g_dec;

// ---------------- helpers ----------------
__device__ __forceinline__ uint32_t smem_u32(const void* p) {
    return (uint32_t)__cvta_generic_to_shared(p);
}
__device__ __forceinline__ uint32_t sw128(uint32_t x) {     // SW128 for 128B rows
    return x ^ ((x >> 3) & 0x70);
}
__device__ __forceinline__ void cp_async16(uint32_t saddr, const void* gaddr) {
    asm volatile("cp.async.cg.shared.global [%0], [%1], 16;" :: "r"(saddr), "l"(gaddr));
}
__device__ __forceinline__ void cp_commit() {
    asm volatile("cp.async.commit_group;" ::: "memory");
}
__device__ __forceinline__ void cp_wait1() {
    asm volatile("cp.async.wait_group 1;" ::: "memory");
}
__device__ __forceinline__ void ldm4(uint32_t& r0, uint32_t& r1, uint32_t& r2, uint32_t& r3,
                                     uint32_t addr) {
    asm volatile("ldmatrix.sync.aligned.m8n8.x4.shared.b16 {%0,%1,%2,%3}, [%4];"
                 : "=r"(r0), "=r"(r1), "=r"(r2), "=r"(r3) : "r"(addr));
}
__device__ __forceinline__ void mma16832(float* c, uint32_t a0, uint32_t a1, uint32_t a2,
                                         uint32_t a3, uint32_t b0, uint32_t b1) {
    asm volatile("mma.sync.aligned.m16n8k32.row.col.f32.e4m3.e4m3.f32 "
                 "{%0,%1,%2,%3}, {%4,%5,%6,%7}, {%8,%9}, {%0,%1,%2,%3};"
                 : "+f"(c[0]), "+f"(c[1]), "+f"(c[2]), "+f"(c[3])
                 : "r"(a0), "r"(a1), "r"(a2), "r"(a3), "r"(b0), "r"(b1));
}
__device__ __forceinline__ uint32_t f2e4m3x2(float hi, float lo) {
    uint32_t u;
    asm("{\n\t.reg .b16 t;\n\tcvt.rn.satfinite.e4m3x2.f32 t, %1, %2;\n\t"
        "cvt.u32.u16 %0, t;\n\t}" : "=r"(u) : "f"(hi), "f"(lo));
    return u;
}

// ---------------- kernels ----------------
// A = e4m3(exp(output_mle)), zero K-padding. Also zeroes scalar accumulators.
__global__ __launch_bounds__(256) void k_convA(const float* __restrict__ mle) {
    if (blockIdx.x == 0 && blockIdx.y == 0 && threadIdx.x == 0) {
        g_cov = 0.f; g_nll = 0.f; g_cnt = 0.f; g_cos = 0.f;
    }
    int k4 = (blockIdx.x * 256 + threadIdx.x) * 4;
    int i = blockIdx.y;
    if (k4 >= KPAD) return;
    const float* row = mle + (size_t)i * Vv;
    float v[4];
    #pragma unroll
    for (int j = 0; j < 4; j++) {
        int k = k4 + j;
        v[j] = (k < Vv) ? __expf(row[k]) : 0.f;
    }
    uint32_t lo = f2e4m3x2(v[1], v[0]);
    uint32_t hi = f2e4m3x2(v[3], v[2]);
    *reinterpret_cast<uint32_t*>(g_A8 + (size_t)i * KPAD + k4) = lo | (hi << 16);
}

// Wt[d][k] = e4m3(256 * W[k][d]), zero K-padding. smem transpose tile 128(k) x 32(d).
__global__ __launch_bounds__(256) void k_convW(const float* __restrict__ W) {
    __shared__ float tile[128][33];
    int kb = blockIdx.x * 128, db = blockIdx.y * 32;
    int t = threadIdx.x;
    {
        int krow = t >> 1, dseg = (t & 1) * 16;
        int k = kb + krow;
        if (k < Vv) {
            const float4* src = reinterpret_cast<const float4*>(W + (size_t)k * Dd + db + dseg);
            #pragma unroll
            for (int j = 0; j < 4; j++) {
                float4 f = src[j];
                tile[krow][dseg + j * 4 + 0] = f.x;
                tile[krow][dseg + j * 4 + 1] = f.y;
                tile[krow][dseg + j * 4 + 2] = f.z;
                tile[krow][dseg + j * 4 + 3] = f.w;
            }
        } else {
            #pragma unroll
            for (int j = 0; j < 16; j++) tile[krow][dseg + j] = 0.f;
        }
    }
    __syncthreads();
    {
        int dl = t >> 3, kseg = (t & 7) * 16;
        uint32_t w[4];
        #pragma unroll
        for (int q = 0; q < 4; q++) {
            float a = tile[kseg + q * 4 + 0][dl] * WSCALE;
            float b = tile[kseg + q * 4 + 1][dl] * WSCALE;
            float c = tile[kseg + q * 4 + 2][dl] * WSCALE;
            float d = tile[kseg + q * 4 + 3][dl] * WSCALE;
            w[q] = f2e4m3x2(b, a) | (f2e4m3x2(d, c) << 16);
        }
        uint4 out = make_uint4(w[0], w[1], w[2], w[3]);
        *reinterpret_cast<uint4*>(g_Wt8 + (size_t)(db + dl) * KPAD + kb + kseg) = out;
    }
}

// NLL + coverage + dec_len reductions
__global__ __launch_bounds__(256) void k_scalars(
    const float* __restrict__ mle, const float* __restrict__ attn,
    const float* __restrict__ covr, const int* __restrict__ trg,
    const int* __restrict__ dmask, const int* __restrict__ dlen) {
    int tid = threadIdx.x;
    const int NCOV4 = Bb * LSRC * Tt / 4;
    float s = 0.f;
    {
        int idx4 = blockIdx.x * 256 + tid;
        if (idx4 < NCOV4) {
            int g = idx4 * 4;
            int b = g / (LSRC * Tt);
            int t0 = g & (Tt - 1);
            float4 a = reinterpret_cast<const float4*>(attn)[idx4];
            float4 c = reinterpret_cast<const float4*>(covr)[idx4];
            const int* mrow = dmask + b * Tt;
            float m0 = mrow[t0]     ? 0.f : 1.f;
            float m1 = mrow[t0 + 1] ? 0.f : 1.f;
            float m2 = mrow[t0 + 2] ? 0.f : 1.f;
            float m3 = mrow[t0 + 3] ? 0.f : 1.f;
            s = fminf(a.x, c.x) * m0 + fminf(a.y, c.y) * m1 +
                fminf(a.z, c.z) * m2 + fminf(a.w, c.w) * m3;
        }
    }
    __shared__ float sm[8];
    #pragma unroll
    for (int o = 16; o > 0; o >>= 1) s += __shfl_down_sync(~0u, s, o);
    if ((tid & 31) == 0) sm[tid >> 5] = s;
    __syncthreads();
    if (tid == 0) {
        float tot = 0.f;
        #pragma unroll
        for (int w = 0; w < 8; w++) tot += sm[w];
        atomicAdd(&g_cov, tot);
    }
    if (blockIdx.x == 0) {
        float ls = 0.f, lc = 0.f;
        for (int j = tid; j < Mm; j += 256) {
            int tg = trg[j];
            if (tg != 0) { ls += logf(mle[(size_t)j * Vv + tg]); lc += 1.f; }
        }
        __shared__ float sa[8], sb2[8];
        #pragma unroll
        for (int o = 16; o > 0; o >>= 1) {
            ls += __shfl_down_sync(~0u, ls, o);
            lc += __shfl_down_sync(~0u, lc, o);
        }
        if ((tid & 31) == 0) { sa[tid >> 5] = ls; sb2[tid >> 5] = lc; }
        __syncthreads();
        if (tid == 0) {
            float a = 0.f, b = 0.f;
            #pragma unroll
            for (int w = 0; w < 8; w++) { a += sa[w]; b += sb2[w]; }
            g_nll = a; g_cnt = b;
            g_dec = (float)(dlen[0] + dlen[1] + dlen[2] + dlen[3]);
        }
    }
}

// ---------------- fp8 mma.sync GEMM ----------------
// part[z] = A[m0:m0+128, kslice] @ Wt[n0:n0+128, kslice]^T   (e4m3 x e4m3 -> f32)
// grid (4, 4, KSPLIT), 512 threads (16 warps, 4 per SMSP).
// Warp grid 4(m) x 4(n), warp tile 32x32, acc = 32 regs/thread.
// 3-stage cp.async pipeline, BK=128B, SW128 smem, ONE __syncthreads per iter.
__global__ __launch_bounds__(512) void k_gemm() {
    extern __shared__ char dsm[];
    uint32_t sb = (smem_u32(dsm) + 1023) & ~1023u;     // 1024-align for SW128
    int tid = threadIdx.x, l = tid & 31, wid = tid >> 5;
    int wm = wid >> 2, wn = wid & 3;                   // 4x4 warps, tile 32x32
    int m0 = blockIdx.x * 128, n0 = blockIdx.y * 128, z = blockIdx.z;
    int it0 = z * SPLIT_ITERS;
    int it1 = min(NKT, it0 + SPLIT_ITERS);
    int niter = it1 - it0;

    const unsigned char* gA = g_A8  + (size_t)m0 * KPAD;
    const unsigned char* gB = g_Wt8 + (size_t)n0 * KPAD;

    // cp.async geometry: 1024 16B-chunks per operand tile, 2 per thread
    uint32_t so[2];
    const unsigned char* pA[2];
    const unsigned char* pB[2];
    #pragma unroll
    for (int i = 0; i < 2; i++) {
        int u = tid + i * 512;
        int row = u >> 3, c = u & 7;
        so[i] = sw128((uint32_t)(row * 128 + c * 16));
        pA[i] = gA + (size_t)row * KPAD + (size_t)it0 * BK + c * 16;
        pB[i] = gB + (size_t)row * KPAD + (size_t)it0 * BK + c * 16;
    }

    auto issue = [&](int buf, int step) {
        uint32_t base = sb + buf * STAGE;
        size_t koff = (size_t)step * BK;
        #pragma unroll
        for (int i = 0; i < 2; i++) {
            cp_async16(base + so[i],         pA[i] + koff);
            cp_async16(base + 16384 + so[i], pB[i] + koff);
        }
    };

    // hoisted swizzled ldmatrix addresses
    int rowA = (l & 15);
    int kbA  = (l >> 4) << 4;
    int nB   = (l & 7) + ((l >> 4) << 3);
    int kbB  = ((l >> 3) & 1) << 4;
    uint32_t swA[2][4], swB[2][4];
    #pragma unroll
    for (int mi = 0; mi < 2; mi++)
        #pragma unroll
        for (int ks = 0; ks < 4; ks++)
            swA[mi][ks] = sw128((uint32_t)((wm * 32 + mi * 16 + rowA) * 128 + ks * 32 + kbA));
    #pragma unroll
    for (int nj = 0; nj < 2; nj++)
        #pragma unroll
        for (int ks = 0; ks < 4; ks++)
            swB[nj][ks] = sw128((uint32_t)((wn * 32 + nj * 16 + nB) * 128 + ks * 32 + kbB)
                                + 16384u);

    float acc[2][4][4];
    #pragma unroll
    for (int a = 0; a < 2; a++)
        #pragma unroll
        for (int b = 0; b < 4; b++)
            #pragma unroll
            for (int c = 0; c < 4; c++) acc[a][b][c] = 0.f;

    issue(0, 0); cp_commit();
    if (niter > 1) issue(1, 1);
    cp_commit();

    for (int s = 0; s < niter; ++s) {
        cp_wait1();
        __syncthreads();                       // stage s ready; compute s-1 done by all
        if (s + 2 < niter) issue((s + 2) % 3, s + 2);
        cp_commit();

        uint32_t base = sb + (s % 3) * STAGE;
        #pragma unroll
        for (int ks = 0; ks < 4; ks++) {
            uint32_t a[2][4], bfr[2][4];
            #pragma unroll
            for (int mi = 0; mi < 2; mi++)
                ldm4(a[mi][0], a[mi][1], a[mi][2], a[mi][3], base + swA[mi][ks]);
            #pragma unroll
            for (int nj = 0; nj < 2; nj++)
                ldm4(bfr[nj][0], bfr[nj][1], bfr[nj][2], bfr[nj][3], base + swB[nj][ks]);
            #pragma unroll
            for (int mi = 0; mi < 2; mi++)
                #pragma unroll
                for (int nb = 0; nb < 4; nb++)
                    mma16832(acc[mi][nb], a[mi][0], a[mi][1], a[mi][2], a[mi][3],
                             bfr[nb >> 1][2 * (nb & 1)], bfr[nb >> 1][2 * (nb & 1) + 1]);
        }
    }

    // epilogue: write 32x32 warp tile to g_part[z]
    #pragma unroll
    for (int mi = 0; mi < 2; mi++) {
        int r = m0 + wm * 32 + mi * 16 + (l >> 2);
        #pragma unroll
        for (int nb = 0; nb < 4; nb++) {
            int col = n0 + wn * 32 + nb * 8 + 2 * (l & 3);
            float* p0 = g_part + ((size_t)z * Mm + r)     * Dd + col;
            float* p1 = g_part + ((size_t)z * Mm + r + 8) * Dd + col;
            *reinterpret_cast<float2*>(p0) = make_float2(acc[mi][nb][0], acc[mi][nb][1]);
            *reinterpret_cast<float2*>(p1) = make_float2(acc[mi][nb][2], acc[mi][nb][3]);
        }
    }
}

// per-row cosine between pred (summed over ksplit partials) and target embedding
__global__ __launch_bounds__(128) void k_rowcos(const float* __restrict__ W,
                                                const int* __restrict__ trg) {
    int i = blockIdx.x;
    const float4* w4 = reinterpret_cast<const float4*>(W + (size_t)trg[i] * Dd);
    float dot = 0.f, np = 0.f, ne = 0.f;
    {
        int d4 = threadIdx.x;                  // Dd/4 = 128 = blockDim
        float4 a = make_float4(0.f, 0.f, 0.f, 0.f);
        #pragma unroll
        for (int zz = 0; zz < KSPLIT; zz++) {
            float4 p = reinterpret_cast<const float4*>(
                g_part + ((size_t)zz * Mm + i) * Dd)[d4];
            a.x += p.x; a.y += p.y; a.z += p.z; a.w += p.w;
        }
        float4 b = w4[d4];
        dot = a.x * b.x + a.y * b.y + a.z * b.z + a.w * b.w;
        np  = a.x * a.x + a.y * a.y + a.z * a.z + a.w * a.w;
        ne  = b.x * b.x + b.y * b.y + b.z * b.z + b.w * b.w;
    }
    __shared__ float s0[4], s1[4], s2[4];
    #pragma unroll
    for (int o = 16; o > 0; o >>= 1) {
        dot += __shfl_down_sync(~0u, dot, o);
        np  += __shfl_down_sync(~0u, np,  o);
        ne  += __shfl_down_sync(~0u, ne,  o);
    }
    int wid = threadIdx.x >> 5, lid = threadIdx.x & 31;
    if (lid == 0) { s0[wid] = dot; s1[wid] = np; s2[wid] = ne; }
    __syncthreads();
    if (threadIdx.x == 0) {
        dot = s0[0] + s0[1] + s0[2] + s0[3];
        np  = s1[0] + s1[1] + s1[2] + s1[3];
        ne  = s2[0] + s2[1] + s2[2] + s2[3];
        atomicAdd(&g_cos, dot * rsqrtf(np * ne));
    }
}

__global__ void k_final(float* out) {
    // loss = nll + GAMMA1*cov_loss + GAMMA2 + ot,  ot = trace(C)/n (IPOT fixed point)
    out[0] = (-g_nll / g_cnt) + (g_cov / g_dec) + 0.1f + g_cos * (1.0f / (float)Mm);
}

// ---------------- launch ----------------
extern "C" void kernel_launch(void* const* d_in, const int* in_sizes, int n_in,
                              void* d_out, int out_size) {
    (void)in_sizes; (void)n_in; (void)out_size;
    const float* mle   = (const float*)d_in[0];   // [B, T, V]
    const float* attn  = (const float*)d_in[1];   // [B, LSRC, T]
    const float* covr  = (const float*)d_in[2];   // [B, LSRC, T]
    const int*   trg   = (const int*)  d_in[3];   // [B, T]
    const int*   dmask = (const int*)  d_in[4];   // [B, T]
    const int*   dlen  = (const int*)  d_in[5];   // [B]
    const float* W     = (const float*)d_in[6];   // [V, D]
    float* out = (float*)d_out;

    cudaFuncSetAttribute(k_gemm, cudaFuncAttributeMaxDynamicSharedMemorySize, GEMM_SMEM);

    k_convA<<<dim3((KPAD / 4 + 255) / 256, Mm), 256>>>(mle);
    k_convW<<<dim3(KPAD / 128, Dd / 32), 256>>>(W);
    k_scalars<<<256, 256>>>(mle, attn, covr, trg, dmask, dlen);
    k_gemm<<<dim3(4, 4, KSPLIT), 512, GEMM_SMEM>>>();
    k_rowcos<<<Mm, 128>>>(W, trg);
    k_final<<<1, 1>>>(out);
}